// round 5
// baseline (speedup 1.0000x reference)
#include <cuda_runtime.h>
#include <math.h>

#define BATCH 8
#define NC 80
#define NA 8400
#define NA0 6400
#define NA1 1600
#define NA2 400
#define PRE_TOPK 5000
#define KMAX 100
#define TOTK (NC*KMAX)
#define SCORE_THR 0.01f
#define IOU_THR 0.65f
#define NTH 256
#define CAP 512
#define BSEL 256
#define FSORT 256
#define PFN 128
#define PADKEY 0xFFFFFFFFFFFFFFFFull
#define FULLM 0xFFFFFFFFu

// ---------------- scratch ----------------
__device__ float g_boxes[BATCH*NA*4];        // [b][a][4] xyxy
__device__ float g_qobj [BATCH*NA];          // 1 + exp(-obj)
__device__ float g_sobj [BATCH*NA];          // exact sigmoid(obj)
__device__ float g_kept_score[BATCH*TOTK];
__device__ float g_kept_box  [BATCH*TOTK*4];

// decision-exact IoU>thr test (IoU symmetric)
__device__ __forceinline__ bool iou_sup(float SX1,float SY1,float SX2,float SY2,float SAR,
                                        float x1,float y1,float x2,float y2,float ar){
    float tlx = fmaxf(SX1, x1), tly = fmaxf(SY1, y1);
    float brx = fminf(SX2, x2), bry = fminf(SY2, y2);
    float ww = fmaxf(brx - tlx, 0.f), hh = fmaxf(bry - tly, 0.f);
    float inter = ww*hh;
    float denom = SAR + ar - inter + 1e-6f;
    float d = inter - IOU_THR*denom;
    if (fabsf(d) > 1e-4f*denom) return d > 0.f;
    return __fdiv_rn(inter, denom) > IOU_THR;
}

// monotone cheap approx of 1+e^{-x} (selection surrogate only)
__device__ __forceinline__ float qapprox(float x){
    float t = fminf(fmaxf(-x, -80.f), 80.f);
    int bits = (int)(12102203.0f*t + 1064986316.0f);
    return 1.0f + __int_as_float(bits);
}

// warp-aggregated histogram add (all lanes of warp must reach this call)
__device__ __forceinline__ void hadd(unsigned* h, unsigned bin, bool pred){
    unsigned pm = __ballot_sync(FULLM, pred);
    if (pred){
        unsigned mm = __match_any_sync(pm, bin);
        int ldr = __ffs(mm) - 1;
        if ((int)(threadIdx.x & 31) == ldr) atomicAdd(&h[bin], (unsigned)__popc(mm));
    }
}

// warp-aggregated compaction append (index payload)
__device__ __forceinline__ void append_idx(unsigned long long* key, int* cnt,
                                           bool pred, unsigned a){
    unsigned pm = __ballot_sync(FULLM, pred);
    if (!pm) return;
    int lane = (int)(threadIdx.x & 31);
    int ldr  = __ffs(pm) - 1;
    int pre  = __popc(pm & ((1u<<lane)-1u));
    int base = 0;
    if (lane == ldr) base = atomicAdd(cnt, __popc(pm));
    base = __shfl_sync(FULLM, base, ldr);
    if (pred){
        int p = base + pre;
        if (p < CAP) key[p] = (unsigned long long)a;
    }
}

// warp-0 collective: scan 256-bin hist, pick bin holding rank kk; early-exit if
// accepting the whole bin keeps count <= accCap. Writes shared outputs.
__device__ __forceinline__ void scan_select(const unsigned* hist, int lane,
        unsigned prefix, int kk, int shift, int accCap,
        unsigned* s_pref, int* s_kkv, int* s_seldone, int* s_total){
    unsigned cc[8]; unsigned sum = 0;
    #pragma unroll
    for (int j = 0; j < 8; j++){ cc[j] = hist[lane*8+j]; sum += cc[j]; }
    unsigned incl = sum;
    #pragma unroll
    for (int off = 1; off < 32; off <<= 1){
        unsigned n = __shfl_up_sync(FULLM, incl, off);
        if (lane >= off) incl += n;
    }
    unsigned excl = incl - sum;
    unsigned total = __shfl_sync(FULLM, incl, 31);
    if (s_total && lane == 0) *s_total = (int)total;
    if ((int)excl < kk && kk <= (int)incl){
        unsigned run = excl;
        #pragma unroll
        for (int j = 0; j < 8; j++){
            if (run + cc[j] >= (unsigned)kk){
                unsigned binv = ((unsigned)(lane*8+j)) << shift;
                if (shift == 0){ *s_pref = prefix | binv; *s_seldone = 1; }
                else if ((int)(run + cc[j]) <= accCap){
                    *s_pref = prefix | binv | ((1u<<shift)-1u); *s_seldone = 1;
                } else { *s_pref = prefix | binv; *s_kkv = kk - (int)run; }
                break;
            }
            run += cc[j];
        }
    }
}

// ---------------- kernel 1: decode boxes + objectness ----------------
__global__ void k_decode(const float* __restrict__ bb0, const float* __restrict__ bb1,
                         const float* __restrict__ bb2,
                         const float* __restrict__ obj0, const float* __restrict__ obj1,
                         const float* __restrict__ obj2){
    int idx = blockIdx.x*blockDim.x + threadIdx.x;
    if (idx >= BATCH*NA) return;
    int a = idx % NA, b = idx / NA;
    float p0,p1,p2,p3, px,py,st, ov;
    if (a < NA0){
        int hw = a; const float* p = bb0 + (size_t)b*4*NA0;
        p0=p[hw]; p1=p[NA0+hw]; p2=p[2*NA0+hw]; p3=p[3*NA0+hw];
        ov = obj0[(size_t)b*NA0 + hw];
        px = (float)(hw % 80) * 8.f;  py = (float)(hw / 80) * 8.f;  st = 8.f;
    } else if (a < NA0+NA1){
        int hw = a - NA0; const float* p = bb1 + (size_t)b*4*NA1;
        p0=p[hw]; p1=p[NA1+hw]; p2=p[2*NA1+hw]; p3=p[3*NA1+hw];
        ov = obj1[(size_t)b*NA1 + hw];
        px = (float)(hw % 40) * 16.f; py = (float)(hw / 40) * 16.f; st = 16.f;
    } else {
        int hw = a - NA0 - NA1; const float* p = bb2 + (size_t)b*4*NA2;
        p0=p[hw]; p1=p[NA2+hw]; p2=p[2*NA2+hw]; p3=p[3*NA2+hw];
        ov = obj2[(size_t)b*NA2 + hw];
        px = (float)(hw % 20) * 32.f; py = (float)(hw / 20) * 32.f; st = 32.f;
    }
    float cx = p0*st + px, cy = p1*st + py;
    float w = expf(p2)*st,  h = expf(p3)*st;
    float4 o;
    o.x = cx - w*0.5f; o.y = cy - h*0.5f; o.z = cx + w*0.5f; o.w = cy + h*0.5f;
    *reinterpret_cast<float4*>(&g_boxes[(size_t)idx*4]) = o;
    float e = expf(-ov);
    g_qobj[idx] = 1.0f + e;
    g_sobj[idx] = 1.0f/(1.0f + e);
}

// ---------------- kernel 2: selection + NMS ----------------
__global__ __launch_bounds__(NTH, 5) void k_nms(
    const float* __restrict__ cls0, const float* __restrict__ cls1,
    const float* __restrict__ cls2){

    extern __shared__ char smraw[];
    unsigned* sc = (unsigned*)smraw;                                       // NA surrogate bits
    unsigned long long* key = (unsigned long long*)(smraw + (size_t)NA*4); // CAP keys
    float4* pbox = (float4*)(smraw + (size_t)NA*4 + (size_t)CAP*8);        // PFN prefetched boxes

    __shared__ float kx1[KMAX], ky1[KMAX], kx2[KMAX], ky2[KMAX], ksc[KMAX], kar[KMAX];
    __shared__ unsigned hist[256];
    __shared__ float cbx1[32], cby1[32], cbx2[32], cby2[32], cbar[32], cbs[32];
    __shared__ unsigned conf[32];
    __shared__ int sup[32];
    __shared__ unsigned s_pref, s_vmask;
    __shared__ int s_kkv, s_total, s_seldone;
    __shared__ int s_cnt, s_kept, s_rank;

    int tid = threadIdx.x;
    int lane = tid & 31, w = tid >> 5;
    int bc  = blockIdx.x;
    int b = bc / NC, c = bc % NC;

    const float* sobj = g_sobj + (size_t)b*NA;
    const float* c0 = cls0 + ((size_t)b*NC + c)*NA0;
    const float* c1 = cls1 + ((size_t)b*NC + c)*NA1;
    const float* c2 = cls2 + ((size_t)b*NC + c)*NA2;

    const unsigned QHI = __float_as_uint(110.0f);  // over-inclusive score>0.01 band

    // ---- bulk surrogate + fused pass-1 histogram (warp-aggregated atomics)
    hist[tid] = 0;
    if (tid == 0){ s_kept = 0; s_rank = 0; }
    __syncthreads();
    {
        const float4* c0v = (const float4*)c0;
        const float4* c1v = (const float4*)c1;
        const float4* c2v = (const float4*)c2;
        const float4* qv0 = (const float4*)(g_qobj + (size_t)b*NA);
        uint4* scv = (uint4*)sc;
        const int NB = (NA/4 + NTH - 1)/NTH;
        for (int it = 0; it < NB; it++){
            int i = it*NTH + tid;
            bool inb = i < NA/4;
            uint4 o = make_uint4(QHI,QHI,QHI,QHI);
            if (inb){
                float4 cv;
                if (i < NA0/4)                cv = c0v[i];
                else if (i < (NA0+NA1)/4)     cv = c1v[i - NA0/4];
                else                          cv = c2v[i - (NA0+NA1)/4];
                float4 qv = qv0[i];
                o.x = __float_as_uint(qapprox(cv.x)*qv.x);
                o.y = __float_as_uint(qapprox(cv.y)*qv.y);
                o.z = __float_as_uint(qapprox(cv.z)*qv.z);
                o.w = __float_as_uint(qapprox(cv.w)*qv.w);
                scv[i] = o;
            }
            hadd(hist, o.x>>24, inb && o.x < QHI);
            hadd(hist, o.y>>24, inb && o.y < QHI);
            hadd(hist, o.z>>24, inb && o.z < QHI);
            hadd(hist, o.w>>24, inb && o.w < QHI);
        }
    }
    __syncthreads();

    unsigned prevT = 0;
    bool first = true, done = false;
    const int NH2 = (NA/2 + NTH - 1)/NTH;
    const uint2* sc2 = (const uint2*)sc;

    while (!done){
        if (!first){
            hist[tid] = 0; __syncthreads();
            for (int it = 0; it < NH2; it++){
                int i = it*NTH + tid;
                bool inb = i < NA/2;
                uint2 v = inb ? sc2[i] : make_uint2(QHI,QHI);
                hadd(hist, v.x>>24, inb && v.x < QHI && v.x > prevT);
                hadd(hist, v.y>>24, inb && v.y < QHI && v.y > prevT);
            }
            __syncthreads();
        }
        if (tid == 0) s_seldone = 0;
        __syncthreads();
        if (tid < 32)
            scan_select(hist, lane, 0u, BSEL, 24, CAP, &s_pref, &s_kkv, &s_seldone, &s_total);
        __syncthreads();
        int total = s_total;
        if (total == 0) break;
        bool takeall = (total <= CAP);
        unsigned T = 0xFFFFFFFFu;

        if (!takeall){
            for (int shift = 16; shift >= 0; shift -= 8){
                if (s_seldone) break;
                unsigned prefix = s_pref; int kk = s_kkv;
                unsigned mask = 0xFFFFFFFFu << (shift+8);
                hist[tid] = 0; __syncthreads();
                for (int it = 0; it < NH2; it++){
                    int i = it*NTH + tid;
                    bool inb = i < NA/2;
                    uint2 v = inb ? sc2[i] : make_uint2(QHI,QHI);
                    hadd(hist, (v.x>>shift)&255u,
                         inb && v.x < QHI && v.x > prevT && (v.x & mask) == prefix);
                    hadd(hist, (v.y>>shift)&255u,
                         inb && v.y < QHI && v.y > prevT && (v.y & mask) == prefix);
                }
                __syncthreads();
                if (tid < 32)
                    scan_select(hist, lane, prefix, kk, shift, CAP - BSEL + kk,
                                &s_pref, &s_kkv, &s_seldone, 0);
                __syncthreads();
            }
            T = s_pref;   // inclusive threshold
        }

        // ---- compact candidate indices (warp-aggregated counter)
        if (tid == 0) s_cnt = 0;
        __syncthreads();
        for (int it = 0; it < NH2; it++){
            int i = it*NTH + tid;
            bool inb = i < NA/2;
            uint2 v = inb ? sc2[i] : make_uint2(QHI,QHI);
            append_idx(key, &s_cnt,
                inb && v.x < QHI && v.x > prevT && (takeall || v.x <= T), (unsigned)(2*i));
            append_idx(key, &s_cnt,
                inb && v.y < QHI && v.y > prevT && (takeall || v.y <= T), (unsigned)(2*i+1));
        }
        __syncthreads();
        int cnt = min(s_cnt, CAP);
        int sortN = (cnt <= 256) ? 256 : 512;

        // ---- recompute EXACT reference score for selected; build sort keys
        for (int p = tid; p < sortN; p += NTH){
            if (p < cnt){
                int a = (int)(unsigned)key[p];
                float cv;
                if (a < NA0) cv = c0[a];
                else if (a < NA0+NA1) cv = c1[a-NA0];
                else cv = c2[a-NA0-NA1];
                float sg = 1.0f/(1.0f+expf(-cv));     // exact sigmoid(cls)
                float s  = sg * sobj[a];              // exact reference score
                if (s > SCORE_THR)
                    key[p] = ((unsigned long long)(~__float_as_uint(s)) << 32) | (unsigned)a;
                else
                    key[p] = PADKEY;
            } else key[p] = PADKEY;
        }
        __syncthreads();

        // ---- bitonic sort ascending: score desc, ties lower index first
        for (int ksz = 2; ksz <= sortN; ksz <<= 1){
            for (int j = ksz >> 1; j > 0; j >>= 1){
                for (int idx = tid; idx < sortN; idx += NTH){
                    int l = idx ^ j;
                    if (l > idx){
                        unsigned long long a0 = key[idx], a1 = key[l];
                        bool up = ((idx & ksz) == 0);
                        if ((a0 > a1) == up){ key[idx] = a1; key[l] = a0; }
                    }
                }
                __syncthreads();
            }
        }

        // ---- prefetch boxes for first PFN sorted candidates
        int pn = min(cnt, PFN);
        for (int p = tid; p < pn; p += NTH){
            unsigned long long k2 = key[p];
            if (k2 != PADKEY){
                int a = (int)(unsigned)(k2 & 0xFFFFFFFFull);
                pbox[p] = *reinterpret_cast<const float4*>(&g_boxes[((size_t)b*NA + a)*4]);
            }
        }
        __syncthreads();

        // ---- greedy NMS over chunks of 32 sorted candidates
        int t0 = 0;
        while (t0 < cnt){
            int K = s_kept, rank = s_rank;
            if (K >= KMAX || rank >= PRE_TOPK) break;
            int chunk_n = min(32, min(cnt - t0, PRE_TOPK - rank));

            if (tid < 32){
                bool lv = lane < chunk_n;
                unsigned long long k2 = lv ? key[t0+lane] : PADKEY;
                bool cvalid = lv && (k2 != PADKEY);
                float4 bb = make_float4(0.f,0.f,0.f,0.f);
                float sval = 0.f;
                if (cvalid){
                    int t = t0 + lane;
                    if (t < pn) bb = pbox[t];
                    else {
                        int a = (int)(unsigned)(k2 & 0xFFFFFFFFull);
                        bb = *reinterpret_cast<const float4*>(&g_boxes[((size_t)b*NA + a)*4]);
                    }
                    sval = __uint_as_float(~(unsigned)(k2>>32));
                }
                cbx1[lane]=bb.x; cby1[lane]=bb.y; cbx2[lane]=bb.z; cby2[lane]=bb.w;
                cbar[lane]=(bb.z-bb.x)*(bb.w-bb.y); cbs[lane]=sval;
                conf[lane]=0; sup[lane]=0;
                unsigned vm = __ballot_sync(FULLM, cvalid);
                if (lane == 0) s_vmask = vm;
            }
            __syncthreads();
            unsigned vm = s_vmask;

            // all 8 warps: kept-suppression + intra-chunk conflict matrix
            {
                int i = lane;
                if ((vm>>i)&1u){
                    float x1=cbx1[i], y1=cby1[i], x2=cbx2[i], y2=cby2[i], ar=cbar[i];
                    bool s = false;
                    for (int m = w; m < K; m += 8)
                        s |= iou_sup(kx1[m],ky1[m],kx2[m],ky2[m],kar[m], x1,y1,x2,y2,ar);
                    if (s) sup[i] = 1;
                    unsigned cf = 0;
                    for (int j = w; j < i; j += 8){
                        if ((vm>>j)&1u){
                            if (iou_sup(cbx1[j],cby1[j],cbx2[j],cby2[j],cbar[j],
                                        x1,y1,x2,y2,ar)) cf |= 1u<<j;
                        }
                    }
                    if (cf) atomicOr(&conf[i], cf);
                }
            }
            __syncthreads();

            if (tid < 32){
                bool base_ok = ((vm>>lane)&1u) && (sup[lane] == 0);
                unsigned myconf = conf[lane];
                unsigned undecided = __ballot_sync(FULLM, base_ok);
                unsigned kept_mask = 0;
                while (undecided){
                    bool und = (undecided >> lane) & 1u;
                    bool decidable = und && ((myconf & undecided & ~(1u<<lane)) == 0);
                    bool keepme = decidable && ((myconf & kept_mask) == 0);
                    unsigned dec = __ballot_sync(FULLM, decidable);
                    unsigned kp  = __ballot_sync(FULLM, keepme);
                    kept_mask |= kp;
                    undecided &= ~dec;
                }
                int pos = K + __popc(kept_mask & ((1u<<lane)-1u));
                if (((kept_mask>>lane)&1u) && pos < KMAX){
                    kx1[pos]=cbx1[lane]; ky1[pos]=cby1[lane];
                    kx2[pos]=cbx2[lane]; ky2[pos]=cby2[lane];
                    kar[pos]=cbar[lane]; ksc[pos]=cbs[lane];
                }
                if (lane == 0){
                    s_kept = min(K + __popc(kept_mask), KMAX);
                    s_rank = rank + chunk_n;
                }
            }
            __syncthreads();
            t0 += 32;
        }
        if (s_kept >= KMAX || s_rank >= PRE_TOPK || takeall) done = true;
        else prevT = T;
        first = false;
        __syncthreads();
    }

    // ---- per-class outputs
    int kept = s_kept;
    float* keptS = g_kept_score + (size_t)bc*KMAX;
    float* keptB = g_kept_box   + (size_t)bc*KMAX*4;
    for (int j = tid; j < KMAX; j += NTH){
        if (j < kept){
            keptS[j] = ksc[j];
            keptB[j*4+0]=kx1[j]; keptB[j*4+1]=ky1[j];
            keptB[j*4+2]=kx2[j]; keptB[j*4+3]=ky2[j];
        } else {
            keptS[j] = -1.f;
            keptB[j*4+0]=0.f; keptB[j*4+1]=0.f; keptB[j*4+2]=0.f; keptB[j*4+3]=0.f;
        }
    }
}

// ---------------- kernel 3: per-image global top-100 ----------------
__global__ __launch_bounds__(NTH) void k_final(float* __restrict__ out){
    __shared__ unsigned mapped[TOTK];
    __shared__ unsigned long long key[FSORT];
    __shared__ unsigned hist[256];
    __shared__ unsigned s_pref; __shared__ int s_kkv, s_seldone;
    __shared__ int s_cnt;

    int tid = threadIdx.x, b = blockIdx.x;
    int lane = tid & 31;
    const float* ks = g_kept_score + (size_t)b*TOTK;
    for (int j = tid; j < TOTK; j += NTH){
        unsigned u = __float_as_uint(ks[j]);
        mapped[j] = (u & 0x80000000u) ? ~u : (u | 0x80000000u);
    }
    __syncthreads();

    // radix select: 100th-largest mapped value (select (TOTK-KMAX+1)-th smallest)
    const int NJ = (TOTK + NTH - 1)/NTH;
    unsigned prefix = 0; int kk = TOTK - KMAX + 1;
    if (tid == 0) s_seldone = 0;
    __syncthreads();
    for (int shift = 24; shift >= 0; shift -= 8){
        unsigned mask = (shift == 24) ? 0u : (0xFFFFFFFFu << (shift+8));
        hist[tid] = 0; __syncthreads();
        for (int it = 0; it < NJ; it++){
            int j = it*NTH + tid;
            bool inb = j < TOTK;
            unsigned v = inb ? mapped[j] : 0u;
            hadd(hist, (v>>shift)&255u, inb && (v & mask) == prefix);
        }
        __syncthreads();
        if (tid < 32){
            unsigned cc[8]; unsigned sum = 0;
            #pragma unroll
            for (int q = 0; q < 8; q++){ cc[q] = hist[lane*8+q]; sum += cc[q]; }
            unsigned incl = sum;
            #pragma unroll
            for (int off = 1; off < 32; off <<= 1){
                unsigned n = __shfl_up_sync(FULLM, incl, off);
                if (lane >= off) incl += n;
            }
            unsigned excl = incl - sum;
            if ((int)excl < kk && kk <= (int)incl){
                unsigned run = excl;
                #pragma unroll
                for (int q = 0; q < 8; q++){
                    if (run + cc[q] >= (unsigned)kk){
                        s_pref = prefix | (((unsigned)(lane*8+q)) << shift);
                        s_kkv  = kk - (int)run;
                        break;
                    }
                    run += cc[q];
                }
            }
        }
        __syncthreads();
        prefix = s_pref; kk = s_kkv;
        __syncthreads();
    }
    unsigned T = prefix;              // kk-th smallest == KMAX-th largest
    const unsigned MAP0 = 0x80000000u;

    if (tid == 0) s_cnt = 0;
    __syncthreads();
    for (int it = 0; it < NJ; it++){
        int j = it*NTH + tid;
        bool inb = j < TOTK;
        unsigned v = inb ? mapped[j] : 0u;
        bool pred = inb && v >= T && v > MAP0;
        unsigned pm = __ballot_sync(FULLM, pred);
        if (pm){
            int ldr = __ffs(pm)-1;
            int pre = __popc(pm & ((1u<<lane)-1u));
            int base = 0;
            if (lane == ldr) base = atomicAdd(&s_cnt, __popc(pm));
            base = __shfl_sync(FULLM, base, ldr);
            if (pred){
                int p = base + pre;
                if (p < FSORT)
                    key[p] = ((unsigned long long)v << 32) | (0xFFFFFFFFu - (unsigned)j);
            }
        }
    }
    __syncthreads();
    int cnt = min(s_cnt, FSORT);
    for (int p = cnt + tid; p < FSORT; p += NTH) key[p] = 0ull;
    __syncthreads();

    for (int ksz = 2; ksz <= FSORT; ksz <<= 1){
        for (int j = ksz >> 1; j > 0; j >>= 1){
            if (tid < FSORT){
                int idx = tid, l = idx ^ j;
                if (l > idx){
                    unsigned long long a0 = key[idx], a1 = key[l];
                    bool up = ((idx & ksz) == 0);
                    if ((a0 > a1) == up){ key[idx] = a1; key[l] = a0; }
                }
            }
            __syncthreads();
        }
    }

    float* out_num = out;
    float* out_box = out + BATCH;
    float* out_sc  = out + BATCH + (size_t)BATCH*KMAX*4;
    float* out_cl  = out + BATCH + (size_t)BATCH*KMAX*4 + (size_t)BATCH*KMAX;

    for (int k = tid; k < KMAX; k += NTH){
        bool valid = (k < cnt);
        float s = 0.f, cl = -1.f, b0=0.f, b1=0.f, b2=0.f, b3=0.f;
        if (valid){
            unsigned long long k2 = key[FSORT-1-k];
            int flat = (int)(0xFFFFFFFFu - (unsigned)(k2 & 0xFFFFFFFFull));
            s  = g_kept_score[(size_t)b*TOTK + flat];
            cl = (float)(flat / KMAX);
            const float* bb = &g_kept_box[((size_t)b*TOTK + flat)*4];
            b0 = bb[0]; b1 = bb[1]; b2 = bb[2]; b3 = bb[3];
        }
        out_sc[(size_t)b*KMAX + k] = s;
        out_cl[(size_t)b*KMAX + k] = cl;
        float* ob = &out_box[((size_t)b*KMAX + k)*4];
        ob[0]=b0; ob[1]=b1; ob[2]=b2; ob[3]=b3;
    }
    if (tid == 0) out_num[b] = (float)min(cnt, KMAX);
}

// ---------------- launch ----------------
extern "C" void kernel_launch(void* const* d_in, const int* in_sizes, int n_in,
                              void* d_out, int out_size){
    const float* cls0 = (const float*)d_in[0];
    const float* bb0  = (const float*)d_in[1];
    const float* obj0 = (const float*)d_in[2];
    const float* cls1 = (const float*)d_in[3];
    const float* bb1  = (const float*)d_in[4];
    const float* obj1 = (const float*)d_in[5];
    const float* cls2 = (const float*)d_in[6];
    const float* bb2  = (const float*)d_in[7];
    const float* obj2 = (const float*)d_in[8];
    float* out = (float*)d_out;

    int n2 = BATCH*NA;
    k_decode<<<(n2+255)/256, 256>>>(bb0, bb1, bb2, obj0, obj1, obj2);

    size_t smem = (size_t)NA*4 + (size_t)CAP*8 + (size_t)PFN*16;   // 39,744 B
    k_nms<<<BATCH*NC, NTH, smem>>>(cls0, cls1, cls2);

    k_final<<<BATCH, NTH>>>(out);
}